// round 14
// baseline (speedup 1.0000x reference)
#include <cuda_runtime.h>
#include <cuda_bf16.h>
#include <cuda_fp16.h>
#include <mma.h>
#include <math.h>
#include <stdint.h>

using namespace nvcuda;

#define NMAX 50000
#define EMAX 800000
#define DDIM 128

// ---------------- device scratch (no allocations allowed) ----------------
__device__ float g_emb [NMAX * DDIM];
__device__ float g_emb2[NMAX * DDIM];
__device__ float g_Q   [NMAX * DDIM];
__device__ __half g_KV [NMAX * 256];    // packed: [node][32 groups][k0..k3, v0..v3]
__device__ int   g_degcur[2 * NMAX + 1];   // deg | cur | hiOr
__device__ int   g_off [NMAX + 1];
__device__ int   g_col [EMAX];
// transposed bf16 weights (hi/lo): Wt[m][k] = W[k][m]
__device__ __nv_bfloat16 g_wh[163840];
__device__ __nv_bfloat16 g_wl[163840];
// pre-converted activations (hi/lo)
__device__ __nv_bfloat16 g_xh[NMAX * 256];
__device__ __nv_bfloat16 g_xl[NMAX * 256];
__device__ __nv_bfloat16 g_eh[NMAX * DDIM];
__device__ __nv_bfloat16 g_el[NMAX * DDIM];

// ---------------- cp.async helpers ----------------
__device__ __forceinline__ void cp16(void* dst, const void* src)
{
    uint32_t d = (uint32_t)__cvta_generic_to_shared(dst);
    asm volatile("cp.async.cg.shared.global [%0], [%1], 16;" :: "r"(d), "l"(src));
}
#define CP_COMMIT() asm volatile("cp.async.commit_group;" ::: "memory")
#define CP_WAIT1()  asm volatile("cp.async.wait_group 1;" ::: "memory")
#define CP_WAIT0()  asm volatile("cp.async.wait_group 0;" ::: "memory")

// prefetch one full 128x128 hi/lo W tile into smem (LDA=136) via cp.async
__device__ __forceinline__ void prefetch_w(const __nv_bfloat16* __restrict__ Wh_o,
                                           const __nv_bfloat16* __restrict__ Wl_o,
                                           __nv_bfloat16* dWh, __nv_bfloat16* dWl, int tid)
{
    #pragma unroll
    for (int it = 0; it < 8; it++) {
        int idx = tid + it * 256;
        int r = idx >> 4, c8 = (idx & 15) * 8;
        size_t g = (size_t)r * 128 + c8;
        cp16(dWh + r * 136 + c8, Wh_o + g);
        cp16(dWl + r * 136 + c8, Wl_o + g);
    }
    CP_COMMIT();
}

// ---------------- CSR build kernels ----------------
__global__ void detect_kernel(const unsigned int* __restrict__ p, int E, int* hiOr)
{
    int i = blockIdx.x * blockDim.x + threadIdx.x;
    int S = (E < 4096) ? E : 4096;
    if (i < S) {
        if (p[2 * i + 1] != 0u) atomicOr(hiOr, 1);
    }
}

__device__ __forceinline__ int eidx_at(const void* p, int i, bool i64)
{
    if (i64) return (int)(((const long long*)p)[i]);
    return ((const int*)p)[i];
}

__global__ void hist_kernel(const void* __restrict__ ei, int E, int n,
                            int* __restrict__ deg, const int* __restrict__ hiOr)
{
    bool i64 = (*hiOr == 0);
    int e = blockIdx.x * blockDim.x + threadIdx.x;
    if (e < E) {
        int r = eidx_at(ei, e, i64);
        if ((unsigned)r < (unsigned)n) atomicAdd(&deg[r], 1);
    }
}

__global__ void scan_kernel(const int* __restrict__ deg, int* __restrict__ off, int n)
{
    __shared__ int warpTot[32];
    const int tid = threadIdx.x;
    const int lane = tid & 31, wid = tid >> 5;
    int carry = 0;
    for (int base = 0; base < n; base += 4096) {
        int i0 = base + tid * 4;
        int v0 = (i0     < n) ? deg[i0]     : 0;
        int v1 = (i0 + 1 < n) ? deg[i0 + 1] : 0;
        int v2 = (i0 + 2 < n) ? deg[i0 + 2] : 0;
        int v3 = (i0 + 3 < n) ? deg[i0 + 3] : 0;
        int s = v0 + v1 + v2 + v3;
        int x = s;
        #pragma unroll
        for (int o = 1; o < 32; o <<= 1) {
            int t = __shfl_up_sync(0xffffffffu, x, o);
            if (lane >= o) x += t;
        }
        if (lane == 31) warpTot[wid] = x;
        __syncthreads();
        if (wid == 0) {
            int y = warpTot[lane];
            #pragma unroll
            for (int o = 1; o < 32; o <<= 1) {
                int t = __shfl_up_sync(0xffffffffu, y, o);
                if (lane >= o) y += t;
            }
            warpTot[lane] = y;
        }
        __syncthreads();
        int wp = (wid == 0) ? 0 : warpTot[wid - 1];
        int excl = carry + wp + x - s;
        if (i0     < n) off[i0]     = excl;
        if (i0 + 1 < n) off[i0 + 1] = excl + v0;
        if (i0 + 2 < n) off[i0 + 2] = excl + v0 + v1;
        if (i0 + 3 < n) off[i0 + 3] = excl + v0 + v1 + v2;
        carry += warpTot[31];
        __syncthreads();
    }
    if (tid == 0) off[n] = carry;
}

__global__ void scatter_kernel(const void* __restrict__ ei, int E, int n,
                               const int* __restrict__ off, int* __restrict__ cur,
                               int* __restrict__ col, const int* __restrict__ hiOr)
{
    bool i64 = (*hiOr == 0);
    int e = blockIdx.x * blockDim.x + threadIdx.x;
    if (e < E) {
        int r = eidx_at(ei, e, i64);
        int c = eidx_at(ei, E + e, i64);
        if ((unsigned)r < (unsigned)n) {
            int pos = off[r] + atomicAdd(&cur[r], 1);
            if ((unsigned)c >= (unsigned)n) c = 0;
            col[pos] = c;
        }
    }
}

// ---------------- weight prep: fp32 W[K,M] -> bf16 hi/lo Wt[M,K] ----------
__global__ void prep_weights(const float* __restrict__ Wp,
                             const float* __restrict__ q1, const float* __restrict__ k1,
                             const float* __restrict__ v1,
                             const float* __restrict__ q2, const float* __restrict__ k2,
                             const float* __restrict__ v2,
                             const float* __restrict__ invw,
                             __nv_bfloat16* __restrict__ wh, __nv_bfloat16* __restrict__ wl)
{
    int idx = blockIdx.x * blockDim.x + threadIdx.x;
    if (idx >= 163840) return;
    const float* src;
    int base, M, K;
    if (idx < 32768)       { src = Wp;   base = 0;      M = 128; K = 256; }
    else if (idx < 131072) {
        int m = (idx - 32768) / 16384;
        const float* arr[6] = {q1, k1, v1, q2, k2, v2};
        src = arr[m]; base = 32768 + m * 16384; M = 128; K = 128;
    }
    else                   { src = invw; base = 131072; M = 256; K = 128; }
    int e = idx - base;
    int m = e / K, k = e - m * K;          // dst index (m, k)
    float v = src[(size_t)k * M + m];
    __nv_bfloat16 hi = __float2bfloat16(v);
    float lo = v - __bfloat162float(hi);
    wh[idx] = hi;
    wl[idx] = __float2bfloat16(lo);
}

// ---------------- activation pre-convert: fp32 -> bf16 hi/lo --------------
__device__ __forceinline__ void split4(float4 v, uint2& hv, uint2& lv)
{
    __nv_bfloat16 hx = __float2bfloat16(v.x);
    __nv_bfloat16 hy = __float2bfloat16(v.y);
    __nv_bfloat16 hz = __float2bfloat16(v.z);
    __nv_bfloat16 hw = __float2bfloat16(v.w);
    __nv_bfloat16 lx = __float2bfloat16(v.x - __bfloat162float(hx));
    __nv_bfloat16 ly = __float2bfloat16(v.y - __bfloat162float(hy));
    __nv_bfloat16 lz = __float2bfloat16(v.z - __bfloat162float(hz));
    __nv_bfloat16 lw = __float2bfloat16(v.w - __bfloat162float(hw));
    hv.x = ((uint32_t)__bfloat16_as_ushort(hy) << 16) | __bfloat16_as_ushort(hx);
    hv.y = ((uint32_t)__bfloat16_as_ushort(hw) << 16) | __bfloat16_as_ushort(hz);
    lv.x = ((uint32_t)__bfloat16_as_ushort(ly) << 16) | __bfloat16_as_ushort(lx);
    lv.y = ((uint32_t)__bfloat16_as_ushort(lw) << 16) | __bfloat16_as_ushort(lz);
}

__global__ void conv_x_kernel(const float* __restrict__ A,
                              __nv_bfloat16* __restrict__ oh, __nv_bfloat16* __restrict__ ol,
                              int total4)
{
    int i = blockIdx.x * blockDim.x + threadIdx.x;
    if (i >= total4) return;
    float4 v = *(const float4*)(A + (size_t)i * 4);
    uint2 hv, lv;
    split4(v, hv, lv);
    *(uint2*)(oh + (size_t)i * 4) = hv;
    *(uint2*)(ol + (size_t)i * 4) = lv;
}

// ---------------- generic WMMA bf16 hi/lo GEMM (KC=64 chunks) -------------
template <int K, bool BIAS>
__global__ void __launch_bounds__(256)
gemm_pre(const __nv_bfloat16* __restrict__ Ah, const __nv_bfloat16* __restrict__ Al,
         const __nv_bfloat16* __restrict__ Wth, const __nv_bfloat16* __restrict__ Wtl,
         const float* __restrict__ b1, const float* __restrict__ b2,
         float* __restrict__ C0,
         __nv_bfloat16* __restrict__ oh, __nv_bfloat16* __restrict__ ol,
         int n, int mout)
{
    constexpr int KC  = 64;
    constexpr int LDA = KC + 8;
    constexpr int NKC = K / KC;
    extern __shared__ __align__(16) char smem[];
    __nv_bfloat16* sAh = (__nv_bfloat16*)smem;
    __nv_bfloat16* sAl = sAh + 128 * LDA;
    __nv_bfloat16* sWh = sAl + 128 * LDA;
    __nv_bfloat16* sWl = sWh + 128 * LDA;

    const int tid = threadIdx.x;
    const int warp = tid >> 5;
    const int wr = warp >> 1;
    const int wc = warp & 1;
    const int rowBase = blockIdx.x * 128;
    const int colBase = blockIdx.y * 128;

    wmma::fragment<wmma::accumulator, 16, 16, 16, float> acc[2][4];
    #pragma unroll
    for (int i = 0; i < 2; i++)
        #pragma unroll
        for (int j = 0; j < 4; j++) wmma::fill_fragment(acc[i][j], 0.0f);

    for (int kc = 0; kc < NKC; kc++) {
        const int k0 = kc * KC;
        #pragma unroll
        for (int it = 0; it < 4; it++) {
            int idx = tid + it * 256;
            int r = idx >> 3, c8 = (idx & 7) * 8;
            int row = rowBase + r;
            uint4 hv = make_uint4(0u, 0u, 0u, 0u), lv = hv;
            if (row < n) {
                size_t g = (size_t)row * K + k0 + c8;
                hv = *(const uint4*)(Ah + g);
                lv = *(const uint4*)(Al + g);
            }
            *(uint4*)(sAh + r * LDA + c8) = hv;
            *(uint4*)(sAl + r * LDA + c8) = lv;
        }
        #pragma unroll
        for (int it = 0; it < 4; it++) {
            int idx = tid + it * 256;
            int r = idx >> 3, c8 = (idx & 7) * 8;
            size_t g = (size_t)(colBase + r) * K + k0 + c8;
            *(uint4*)(sWh + r * LDA + c8) = *(const uint4*)(Wth + g);
            *(uint4*)(sWl + r * LDA + c8) = *(const uint4*)(Wtl + g);
        }
        __syncthreads();

        #pragma unroll
        for (int ks = 0; ks < KC / 16; ks++) {
            wmma::fragment<wmma::matrix_a, 16, 16, 16, __nv_bfloat16, wmma::row_major> ah[2], al[2];
            wmma::fragment<wmma::matrix_b, 16, 16, 16, __nv_bfloat16, wmma::col_major> bh[4], bl[4];
            #pragma unroll
            for (int i = 0; i < 2; i++) {
                const __nv_bfloat16* p = sAh + (wr * 32 + i * 16) * LDA + ks * 16;
                wmma::load_matrix_sync(ah[i], p, LDA);
                wmma::load_matrix_sync(al[i], p + 128 * LDA, LDA);
            }
            #pragma unroll
            for (int j = 0; j < 4; j++) {
                const __nv_bfloat16* p = sWh + (wc * 64 + j * 16) * LDA + ks * 16;
                wmma::load_matrix_sync(bh[j], p, LDA);
                wmma::load_matrix_sync(bl[j], p + 128 * LDA, LDA);
            }
            #pragma unroll
            for (int i = 0; i < 2; i++)
                #pragma unroll
                for (int j = 0; j < 4; j++) {
                    wmma::mma_sync(acc[i][j], ah[i], bh[j], acc[i][j]);
                    wmma::mma_sync(acc[i][j], ah[i], bl[j], acc[i][j]);
                    wmma::mma_sync(acc[i][j], al[i], bh[j], acc[i][j]);
                }
        }
        __syncthreads();
    }

    float* sC = (float*)smem;                    // 128 x 132
    #pragma unroll
    for (int i = 0; i < 2; i++)
        #pragma unroll
        for (int j = 0; j < 4; j++)
            wmma::store_matrix_sync(sC + (wr * 32 + i * 16) * 132 + wc * 64 + j * 16,
                                    acc[i][j], 132, wmma::mem_row_major);
    __syncthreads();
    #pragma unroll
    for (int it = 0; it < 16; it++) {
        int idx = tid + it * 256;
        int r = idx >> 5, c4 = (idx & 31) * 4;
        int row = rowBase + r;
        if (row < n) {
            float4 v = *(float4*)(sC + r * 132 + c4);
            if (BIAS) {
                int col = colBase + c4;
                v.x += b1[col];     v.y += b1[col + 1];
                v.z += b1[col + 2]; v.w += b1[col + 3];
                if (b2) {
                    v.x += b2[col];     v.y += b2[col + 1];
                    v.z += b2[col + 2]; v.w += b2[col + 3];
                }
            }
            size_t g = (size_t)row * mout + colBase + c4;
            *(float4*)(C0 + g) = v;
            if (oh) {
                uint2 hv, lv;
                split4(v, hv, lv);
                *(uint2*)(oh + g) = hv;
                *(uint2*)(ol + g) = lv;
            }
        }
    }
}

// ---------------- fused QKV GEMM: A resident, cp.async W double-buffer ----
// K = 128. o=0 -> fp32 Q; o=1 (K), o=2 (V) -> packed fp16 KV.
// smem: A hi/lo (69632) + 2 W buffers (69632 each) = 208896 bytes.
__global__ void __launch_bounds__(256)
gemm_qkv(const __nv_bfloat16* __restrict__ Ah, const __nv_bfloat16* __restrict__ Al,
         const __nv_bfloat16* __restrict__ Wth, const __nv_bfloat16* __restrict__ Wtl,
         float* __restrict__ Qout, __half* __restrict__ kvout, int n)
{
    constexpr int K   = 128;
    constexpr int LDA = K + 8;          // 136
    extern __shared__ __align__(16) char smem[];
    __nv_bfloat16* sAh  = (__nv_bfloat16*)smem;           // 128*136 x2 (hi+lo)
    __nv_bfloat16* sAl  = sAh + 128 * LDA;
    __nv_bfloat16* buf0 = sAl + 128 * LDA;                // W buffer 0 (hi then lo)
    __nv_bfloat16* buf1 = buf0 + 2 * 128 * LDA;           // W buffer 1

    const int tid = threadIdx.x;
    const int warp = tid >> 5;
    const int wr = warp >> 1;
    const int wc = warp & 1;
    const int rowBase = blockIdx.x * 128;

    // prefetch W0 -> buf0, W1 -> buf1 (flights overlap the A staging below)
    prefetch_w(Wth,             Wtl,             buf0, buf0 + 128 * LDA, tid);
    prefetch_w(Wth + K * 128,   Wtl + K * 128,   buf1, buf1 + 128 * LDA, tid);

    // stage full A (hi/lo) once (regular loads; zero-fill OOB rows)
    #pragma unroll
    for (int it = 0; it < 8; it++) {
        int idx = tid + it * 256;               // 2048 uint4 per buffer
        int r = idx >> 4, c8 = (idx & 15) * 8;
        int row = rowBase + r;
        uint4 hv = make_uint4(0u, 0u, 0u, 0u), lv = hv;
        if (row < n) {
            size_t g = (size_t)row * K + c8;
            hv = *(const uint4*)(Ah + g);
            lv = *(const uint4*)(Al + g);
        }
        *(uint4*)(sAh + r * LDA + c8) = hv;
        *(uint4*)(sAl + r * LDA + c8) = lv;
    }

    for (int o = 0; o < 3; o++) {
        if (o < 2) CP_WAIT1(); else CP_WAIT0();
        __syncthreads();          // W_o landed in all threads' view; A staged

        __nv_bfloat16* sWh = (o & 1) ? buf1 : buf0;
        __nv_bfloat16* sWl = sWh + 128 * LDA;

        wmma::fragment<wmma::accumulator, 16, 16, 16, float> acc[2][4];
        #pragma unroll
        for (int i = 0; i < 2; i++)
            #pragma unroll
            for (int j = 0; j < 4; j++) wmma::fill_fragment(acc[i][j], 0.0f);

        #pragma unroll
        for (int ks = 0; ks < 8; ks++) {
            wmma::fragment<wmma::matrix_a, 16, 16, 16, __nv_bfloat16, wmma::row_major> ah[2], al[2];
            wmma::fragment<wmma::matrix_b, 16, 16, 16, __nv_bfloat16, wmma::col_major> bh[4], bl[4];
            #pragma unroll
            for (int i = 0; i < 2; i++) {
                const __nv_bfloat16* p = sAh + (wr * 32 + i * 16) * LDA + ks * 16;
                wmma::load_matrix_sync(ah[i], p, LDA);
                wmma::load_matrix_sync(al[i], p + 128 * LDA, LDA);
            }
            #pragma unroll
            for (int j = 0; j < 4; j++) {
                const __nv_bfloat16* p = sWh + (wc * 64 + j * 16) * LDA + ks * 16;
                wmma::load_matrix_sync(bh[j], p, LDA);
                wmma::load_matrix_sync(bl[j], p + 128 * LDA, LDA);
            }
            #pragma unroll
            for (int i = 0; i < 2; i++)
                #pragma unroll
                for (int j = 0; j < 4; j++) {
                    wmma::mma_sync(acc[i][j], ah[i], bh[j], acc[i][j]);
                    wmma::mma_sync(acc[i][j], ah[i], bl[j], acc[i][j]);
                    wmma::mma_sync(acc[i][j], al[i], bh[j], acc[i][j]);
                }
        }
        __syncthreads();          // all MMA reads of sW done before sC overwrite

        float* sC = (float*)sWh;                     // reuse consumed W buffer
        #pragma unroll
        for (int i = 0; i < 2; i++)
            #pragma unroll
            for (int j = 0; j < 4; j++)
                wmma::store_matrix_sync(sC + (wr * 32 + i * 16) * 132 + wc * 64 + j * 16,
                                        acc[i][j], 132, wmma::mem_row_major);
        __syncthreads();

        #pragma unroll
        for (int it = 0; it < 16; it++) {
            int idx = tid + it * 256;
            int r = idx >> 5, c4 = (idx & 31) * 4;
            int row = rowBase + r;
            if (row < n) {
                float4 v = *(float4*)(sC + r * 132 + c4);
                if (o == 0) {
                    *(float4*)(Qout + (size_t)row * 128 + c4) = v;
                } else {
                    __half2 h01 = __floats2half2_rn(v.x, v.y);
                    __half2 h23 = __floats2half2_rn(v.z, v.w);
                    uint2 st;
                    st.x = *(uint32_t*)&h01;
                    st.y = *(uint32_t*)&h23;
                    *(uint2*)(kvout + (size_t)row * 256 + (c4 >> 2) * 8 + ((o == 1) ? 0 : 4)) = st;
                }
            }
        }
        __syncthreads();          // epilogue reads of sC done before buffer reuse
        if (o == 0)               // prefetch W2 into buf0 (now free)
            prefetch_w(Wth + 2 * K * 128, Wtl + 2 * K * 128, buf0, buf0 + 128 * LDA, tid);
    }
}

// ---------------- final GEMM: A resident, cp.async W double-buffer --------
__global__ void __launch_bounds__(256)
gemm_fin(const __nv_bfloat16* __restrict__ Ah, const __nv_bfloat16* __restrict__ Al,
         const __nv_bfloat16* __restrict__ Wth, const __nv_bfloat16* __restrict__ Wtl,
         const float* __restrict__ bias, float* __restrict__ C, int n)
{
    constexpr int K   = 128;
    constexpr int LDA = K + 8;          // 136
    extern __shared__ __align__(16) char smem[];
    __nv_bfloat16* sAh  = (__nv_bfloat16*)smem;
    __nv_bfloat16* sAl  = sAh + 128 * LDA;
    __nv_bfloat16* buf0 = sAl + 128 * LDA;
    __nv_bfloat16* buf1 = buf0 + 2 * 128 * LDA;

    const int tid = threadIdx.x;
    const int warp = tid >> 5;
    const int wr = warp >> 1;
    const int wc = warp & 1;
    const int rowBase = blockIdx.x * 128;

    prefetch_w(Wth,           Wtl,           buf0, buf0 + 128 * LDA, tid);
    prefetch_w(Wth + K * 128, Wtl + K * 128, buf1, buf1 + 128 * LDA, tid);

    #pragma unroll
    for (int it = 0; it < 8; it++) {
        int idx = tid + it * 256;
        int r = idx >> 4, c8 = (idx & 15) * 8;
        int row = rowBase + r;
        uint4 hv = make_uint4(0u, 0u, 0u, 0u), lv = hv;
        if (row < n) {
            size_t g = (size_t)row * K + c8;
            hv = *(const uint4*)(Ah + g);
            lv = *(const uint4*)(Al + g);
        }
        *(uint4*)(sAh + r * LDA + c8) = hv;
        *(uint4*)(sAl + r * LDA + c8) = lv;
    }

    for (int o = 0; o < 2; o++) {
        if (o == 0) CP_WAIT1(); else CP_WAIT0();
        __syncthreads();

        __nv_bfloat16* sWh = (o & 1) ? buf1 : buf0;
        __nv_bfloat16* sWl = sWh + 128 * LDA;

        wmma::fragment<wmma::accumulator, 16, 16, 16, float> acc[2][4];
        #pragma unroll
        for (int i = 0; i < 2; i++)
            #pragma unroll
            for (int j = 0; j < 4; j++) wmma::fill_fragment(acc[i][j], 0.0f);

        #pragma unroll
        for (int ks = 0; ks < 8; ks++) {
            wmma::fragment<wmma::matrix_a, 16, 16, 16, __nv_bfloat16, wmma::row_major> ah[2], al[2];
            wmma::fragment<wmma::matrix_b, 16, 16, 16, __nv_bfloat16, wmma::col_major> bh[4], bl[4];
            #pragma unroll
            for (int i = 0; i < 2; i++) {
                const __nv_bfloat16* p = sAh + (wr * 32 + i * 16) * LDA + ks * 16;
                wmma::load_matrix_sync(ah[i], p, LDA);
                wmma::load_matrix_sync(al[i], p + 128 * LDA, LDA);
            }
            #pragma unroll
            for (int j = 0; j < 4; j++) {
                const __nv_bfloat16* p = sWh + (wc * 64 + j * 16) * LDA + ks * 16;
                wmma::load_matrix_sync(bh[j], p, LDA);
                wmma::load_matrix_sync(bl[j], p + 128 * LDA, LDA);
            }
            #pragma unroll
            for (int i = 0; i < 2; i++)
                #pragma unroll
                for (int j = 0; j < 4; j++) {
                    wmma::mma_sync(acc[i][j], ah[i], bh[j], acc[i][j]);
                    wmma::mma_sync(acc[i][j], ah[i], bl[j], acc[i][j]);
                    wmma::mma_sync(acc[i][j], al[i], bh[j], acc[i][j]);
                }
        }
        __syncthreads();

        float* sC = (float*)sWh;
        #pragma unroll
        for (int i = 0; i < 2; i++)
            #pragma unroll
            for (int j = 0; j < 4; j++)
                wmma::store_matrix_sync(sC + (wr * 32 + i * 16) * 132 + wc * 64 + j * 16,
                                        acc[i][j], 132, wmma::mem_row_major);
        __syncthreads();

        #pragma unroll
        for (int it = 0; it < 16; it++) {
            int idx = tid + it * 256;
            int r = idx >> 5, c4 = (idx & 31) * 4;
            int row = rowBase + r;
            if (row < n) {
                float4 v = *(float4*)(sC + r * 132 + c4);
                int col = o * 128 + c4;
                v.x += bias[col];     v.y += bias[col + 1];
                v.z += bias[col + 2]; v.w += bias[col + 3];
                *(float4*)(C + (size_t)row * 256 + col) = v;
            }
        }
        __syncthreads();
    }
}

// ---------------- warp-per-node agg + residual + LayerNorm (MLP=4) -------
__device__ __forceinline__ void agg_edge(uint4 kv, float4 q4, float4& acc, float& den)
{
    float2 kf0 = __half22float2(*(const __half2*)&kv.x);
    float2 kf1 = __half22float2(*(const __half2*)&kv.y);
    float2 vf0 = __half22float2(*(const __half2*)&kv.z);
    float2 vf1 = __half22float2(*(const __half2*)&kv.w);
    float d = q4.x * kf0.x;
    d = fmaf(q4.y, kf0.y, d);
    d = fmaf(q4.z, kf1.x, d);
    d = fmaf(q4.w, kf1.y, d);
    d += __shfl_xor_sync(0xffffffffu, d, 1);
    d += __shfl_xor_sync(0xffffffffu, d, 2);
    d = fminf(10.f, fmaxf(-10.f, d));
    float w = __expf(d);
    den += w;
    acc.x = fmaf(w, vf0.x, acc.x);
    acc.y = fmaf(w, vf0.y, acc.y);
    acc.z = fmaf(w, vf1.x, acc.z);
    acc.w = fmaf(w, vf1.y, acc.w);
}

__launch_bounds__(256)
__global__ void agg_ln_kernel(const float* __restrict__ Q, const __half* __restrict__ KV,
                              const float* __restrict__ emb,
                              const int* __restrict__ off, const int* __restrict__ colArr,
                              const float* __restrict__ lns, const float* __restrict__ lnb,
                              float* __restrict__ outp,
                              __nv_bfloat16* __restrict__ oh, __nv_bfloat16* __restrict__ ol,
                              int n)
{
    int gw = (blockIdx.x * blockDim.x + threadIdx.x) >> 5;   // node id
    int lane = threadIdx.x & 31;
    if (gw >= n) return;
    const int base = gw * DDIM + lane * 4;
    const int koff = lane * 8;

    const float4 q4 = *(const float4*)(Q + base);
    float4 acc = make_float4(0.f, 0.f, 0.f, 0.f);
    float den = 0.f;

    int s = off[gw], e = off[gw + 1];
    int i = s;
    for (; i + 4 <= e; i += 4) {
        uint4 kv0 = *(const uint4*)(KV + (size_t)colArr[i]     * 256 + koff);
        uint4 kv1 = *(const uint4*)(KV + (size_t)colArr[i + 1] * 256 + koff);
        uint4 kv2 = *(const uint4*)(KV + (size_t)colArr[i + 2] * 256 + koff);
        uint4 kv3 = *(const uint4*)(KV + (size_t)colArr[i + 3] * 256 + koff);
        agg_edge(kv0, q4, acc, den);
        agg_edge(kv1, q4, acc, den);
        agg_edge(kv2, q4, acc, den);
        agg_edge(kv3, q4, acc, den);
    }
    for (; i < e; i++) {
        uint4 kv = *(const uint4*)(KV + (size_t)colArr[i] * 256 + koff);
        agg_edge(kv, q4, acc, den);
    }

    float inv = 1.f / (den + 1e-8f);
    float4 r = *(const float4*)(emb + base);
    r.x = fmaf(acc.x, inv, r.x);
    r.y = fmaf(acc.y, inv, r.y);
    r.z = fmaf(acc.z, inv, r.z);
    r.w = fmaf(acc.w, inv, r.w);

    float ss = r.x + r.y + r.z + r.w;
    #pragma unroll
    for (int o = 16; o; o >>= 1) ss += __shfl_xor_sync(0xffffffffu, ss, o);
    float mu = ss * (1.f / 128.f);

    float dx = r.x - mu, dy = r.y - mu, dz = r.z - mu, dw = r.w - mu;
    float vs = dx * dx + dy * dy + dz * dz + dw * dw;
    #pragma unroll
    for (int o = 16; o; o >>= 1) vs += __shfl_xor_sync(0xffffffffu, vs, o);
    float var = vs * (1.f / 128.f);
    float rstd = rsqrtf(var + 1e-6f);

    const float4 s4 = *(const float4*)(lns + lane * 4);
    const float4 b4 = *(const float4*)(lnb + lane * 4);
    float4 o4;
    o4.x = dx * rstd * s4.x + b4.x;
    o4.y = dy * rstd * s4.y + b4.y;
    o4.z = dz * rstd * s4.z + b4.z;
    o4.w = dw * rstd * s4.w + b4.w;
    if (outp) *(float4*)(outp + base) = o4;
    uint2 hv, lv;
    split4(o4, hv, lv);
    *(uint2*)(oh + base) = hv;
    *(uint2*)(ol + base) = lv;
}

// ---------------- launch ----------------
extern "C" void kernel_launch(void* const* d_in, const int* in_sizes, int n_in,
                              void* d_out, int out_size)
{
    const float* x    = (const float*)d_in[0];
    const void*  ei   = d_in[1];
    const float* Wp   = (const float*)d_in[2];
    const float* Wpb  = (const float*)d_in[3];
    const float* Wpos = (const float*)d_in[4];
    const float* q1   = (const float*)d_in[5];
    const float* k1   = (const float*)d_in[6];
    const float* v1   = (const float*)d_in[7];
    const float* l1s  = (const float*)d_in[8];
    const float* l1b  = (const float*)d_in[9];
    const float* q2   = (const float*)d_in[10];
    const float* k2   = (const float*)d_in[11];
    const float* v2   = (const float*)d_in[12];
    const float* l2s  = (const float*)d_in[13];
    const float* l2b  = (const float*)d_in[14];
    const float* invw = (const float*)d_in[15];
    const float* invb = (const float*)d_in[16];

    const int D   = in_sizes[3];            // 128
    const int GIN = in_sizes[2] / D;        // 256
    int n = in_sizes[0] / GIN;              // 50000
    int E = in_sizes[1] / 2;                // 800000
    if (n > NMAX) n = NMAX;
    if (E > EMAX) E = EMAX;
    (void)D; (void)n_in; (void)out_size;

    float *emb, *emb2, *Qb;
    __half *kv;
    int *degcur, *off, *col;
    __nv_bfloat16 *wh, *wl, *xh, *xl, *eh, *el;
    cudaGetSymbolAddress((void**)&emb,    g_emb);
    cudaGetSymbolAddress((void**)&emb2,   g_emb2);
    cudaGetSymbolAddress((void**)&Qb,     g_Q);
    cudaGetSymbolAddress((void**)&kv,     g_KV);
    cudaGetSymbolAddress((void**)&degcur, g_degcur);
    cudaGetSymbolAddress((void**)&off,    g_off);
    cudaGetSymbolAddress((void**)&col,    g_col);
    cudaGetSymbolAddress((void**)&wh,     g_wh);
    cudaGetSymbolAddress((void**)&wl,     g_wl);
    cudaGetSymbolAddress((void**)&xh,     g_xh);
    cudaGetSymbolAddress((void**)&xl,     g_xl);
    cudaGetSymbolAddress((void**)&eh,     g_eh);
    cudaGetSymbolAddress((void**)&el,     g_el);
    int* deg  = degcur;
    int* cur  = degcur + NMAX;
    int* hiOr = degcur + 2 * NMAX;

    const int SMEM_G = 4 * 128 * 72 * 2;    // 73728 (generic, KC=64)
    const int SMEM_Q = 6 * 128 * 136 * 2;   // 208896 (A + 2 W buffers)
    cudaFuncSetAttribute(gemm_pre<256, true>,
                         cudaFuncAttributeMaxDynamicSharedMemorySize, SMEM_G);
    cudaFuncSetAttribute(gemm_qkv,
                         cudaFuncAttributeMaxDynamicSharedMemorySize, SMEM_Q);
    cudaFuncSetAttribute(gemm_fin,
                         cudaFuncAttributeMaxDynamicSharedMemorySize, SMEM_Q);

    const int eb  = (E + 255) / 256;
    const int gb  = (n + 127) / 128;
    const int ab  = (n + 7) / 8;

    // Streams/events: created ONCE on first call and reused (per-call creation
    // leaked driver pool memory and tripped the allocation guard).
    static cudaStream_t s2 = nullptr, s3 = nullptr;
    static cudaEvent_t evFork = nullptr, evJoin = nullptr, evConv = nullptr;
    if (s2 == nullptr) {
        cudaStreamCreateWithFlags(&s2, cudaStreamNonBlocking);
        cudaStreamCreateWithFlags(&s3, cudaStreamNonBlocking);
        cudaEventCreateWithFlags(&evFork, cudaEventDisableTiming);
        cudaEventCreateWithFlags(&evJoin, cudaEventDisableTiming);
        cudaEventCreateWithFlags(&evConv, cudaEventDisableTiming);
    }

    cudaEventRecord(evFork, 0);
    cudaStreamWaitEvent(s2, evFork, 0);
    cudaStreamWaitEvent(s3, evFork, 0);

    // --- CSR branch (stream s2) ---
    cudaMemsetAsync(degcur, 0, (size_t)(2 * NMAX + 1) * sizeof(int), s2);
    detect_kernel<<<16, 256, 0, s2>>>((const unsigned int*)ei, E, hiOr);
    hist_kernel<<<eb, 256, 0, s2>>>(ei, E, n, deg, hiOr);
    scan_kernel<<<1, 1024, 0, s2>>>(deg, off, n);
    scatter_kernel<<<eb, 256, 0, s2>>>(ei, E, n, off, cur, col, hiOr);
    cudaEventRecord(evJoin, s2);

    // --- x conversion branch (stream s3, concurrent with prep_weights) ---
    const int xq = n * GIN / 4;
    conv_x_kernel<<<(xq + 255) / 256, 256, 0, s3>>>(x, xh, xl, xq);
    cudaEventRecord(evConv, s3);

    // --- main branch (default stream) ---
    prep_weights<<<640, 256>>>(Wp, q1, k1, v1, q2, k2, v2, invw, wh, wl);
    cudaStreamWaitEvent(0, evConv, 0);

    // input projection + bias + positional embedding (emits emb fp32 + hi/lo)
    gemm_pre<256, true><<<dim3(gb, 1), 256, SMEM_G>>>(
        xh, xl, wh, wl, Wpb, Wpos, emb, eh, el, n, 128);

    // layer 1 QKV (does not need CSR)
    gemm_qkv<<<gb, 256, SMEM_Q>>>(eh, el, wh + 32768, wl + 32768, Qb, kv, n);

    // join: aggregation needs off/col
    cudaStreamWaitEvent(0, evJoin, 0);
    agg_ln_kernel<<<ab, 256>>>(Qb, kv, emb, off, col, l1s, l1b, emb2, eh, el, n);

    // layer 2 (agg2 writes only hi/lo — fp32 output unused downstream)
    gemm_qkv<<<gb, 256, SMEM_Q>>>(eh, el, wh + 81920, wl + 81920, Qb, kv, n);
    agg_ln_kernel<<<ab, 256>>>(Qb, kv, emb2, off, col, l2s, l2b, nullptr, eh, el, n);

    // output projection: A resident, cp.async W double-buffer
    gemm_fin<<<gb, 256, SMEM_Q>>>(
        eh, el, wh + 131072, wl + 131072, invb, (float*)d_out, n);
}

// round 15
// speedup vs baseline: 1.0413x; 1.0413x over previous
#include <cuda_runtime.h>
#include <cuda_bf16.h>
#include <cuda_fp16.h>
#include <mma.h>
#include <math.h>
#include <stdint.h>

using namespace nvcuda;

#define NMAX 50000
#define EMAX 800000
#define DDIM 128

// ---------------- device scratch (no allocations allowed) ----------------
__device__ float g_emb [NMAX * DDIM];
__device__ float g_emb2[NMAX * DDIM];
__device__ float g_Q   [NMAX * DDIM];
__device__ __half g_KV [NMAX * 256];    // packed: [node][32 groups][k0..k3, v0..v3]
__device__ int   g_degcur[2 * NMAX + 1];   // deg | cur | hiOr
__device__ int   g_off [NMAX + 1];
__device__ int   g_col [EMAX];
// transposed bf16 weights (hi/lo): Wt[m][k] = W[k][m]
__device__ __nv_bfloat16 g_wh[163840];
__device__ __nv_bfloat16 g_wl[163840];
// pre-converted activations (hi/lo)
__device__ __nv_bfloat16 g_xh[NMAX * 256];
__device__ __nv_bfloat16 g_xl[NMAX * 256];
__device__ __nv_bfloat16 g_eh[NMAX * DDIM];
__device__ __nv_bfloat16 g_el[NMAX * DDIM];

// ---------------- CSR build kernels ----------------
__global__ void detect_kernel(const unsigned int* __restrict__ p, int E, int* hiOr)
{
    int i = blockIdx.x * blockDim.x + threadIdx.x;
    int S = (E < 4096) ? E : 4096;
    if (i < S) {
        if (p[2 * i + 1] != 0u) atomicOr(hiOr, 1);
    }
}

__device__ __forceinline__ int eidx_at(const void* p, int i, bool i64)
{
    if (i64) return (int)(((const long long*)p)[i]);
    return ((const int*)p)[i];
}

__global__ void hist_kernel(const void* __restrict__ ei, int E, int n,
                            int* __restrict__ deg, const int* __restrict__ hiOr)
{
    bool i64 = (*hiOr == 0);
    int e = blockIdx.x * blockDim.x + threadIdx.x;
    if (e < E) {
        int r = eidx_at(ei, e, i64);
        if ((unsigned)r < (unsigned)n) atomicAdd(&deg[r], 1);
    }
}

__global__ void scan_kernel(const int* __restrict__ deg, int* __restrict__ off, int n)
{
    __shared__ int warpTot[32];
    const int tid = threadIdx.x;
    const int lane = tid & 31, wid = tid >> 5;
    int carry = 0;
    for (int base = 0; base < n; base += 4096) {
        int i0 = base + tid * 4;
        int v0 = (i0     < n) ? deg[i0]     : 0;
        int v1 = (i0 + 1 < n) ? deg[i0 + 1] : 0;
        int v2 = (i0 + 2 < n) ? deg[i0 + 2] : 0;
        int v3 = (i0 + 3 < n) ? deg[i0 + 3] : 0;
        int s = v0 + v1 + v2 + v3;
        int x = s;
        #pragma unroll
        for (int o = 1; o < 32; o <<= 1) {
            int t = __shfl_up_sync(0xffffffffu, x, o);
            if (lane >= o) x += t;
        }
        if (lane == 31) warpTot[wid] = x;
        __syncthreads();
        if (wid == 0) {
            int y = warpTot[lane];
            #pragma unroll
            for (int o = 1; o < 32; o <<= 1) {
                int t = __shfl_up_sync(0xffffffffu, y, o);
                if (lane >= o) y += t;
            }
            warpTot[lane] = y;
        }
        __syncthreads();
        int wp = (wid == 0) ? 0 : warpTot[wid - 1];
        int excl = carry + wp + x - s;
        if (i0     < n) off[i0]     = excl;
        if (i0 + 1 < n) off[i0 + 1] = excl + v0;
        if (i0 + 2 < n) off[i0 + 2] = excl + v0 + v1;
        if (i0 + 3 < n) off[i0 + 3] = excl + v0 + v1 + v2;
        carry += warpTot[31];
        __syncthreads();
    }
    if (tid == 0) off[n] = carry;
}

__global__ void scatter_kernel(const void* __restrict__ ei, int E, int n,
                               const int* __restrict__ off, int* __restrict__ cur,
                               int* __restrict__ col, const int* __restrict__ hiOr)
{
    bool i64 = (*hiOr == 0);
    int e = blockIdx.x * blockDim.x + threadIdx.x;
    if (e < E) {
        int r = eidx_at(ei, e, i64);
        int c = eidx_at(ei, E + e, i64);
        if ((unsigned)r < (unsigned)n) {
            int pos = off[r] + atomicAdd(&cur[r], 1);
            if ((unsigned)c >= (unsigned)n) c = 0;
            col[pos] = c;
        }
    }
}

// ---------------- weight prep: fp32 W[K,M] -> bf16 hi/lo Wt[M,K] ----------
__global__ void prep_weights(const float* __restrict__ Wp,
                             const float* __restrict__ q1, const float* __restrict__ k1,
                             const float* __restrict__ v1,
                             const float* __restrict__ q2, const float* __restrict__ k2,
                             const float* __restrict__ v2,
                             const float* __restrict__ invw,
                             __nv_bfloat16* __restrict__ wh, __nv_bfloat16* __restrict__ wl)
{
    int idx = blockIdx.x * blockDim.x + threadIdx.x;
    if (idx >= 163840) return;
    const float* src;
    int base, M, K;
    if (idx < 32768)       { src = Wp;   base = 0;      M = 128; K = 256; }
    else if (idx < 131072) {
        int m = (idx - 32768) / 16384;
        const float* arr[6] = {q1, k1, v1, q2, k2, v2};
        src = arr[m]; base = 32768 + m * 16384; M = 128; K = 128;
    }
    else                   { src = invw; base = 131072; M = 256; K = 128; }
    int e = idx - base;
    int m = e / K, k = e - m * K;          // dst index (m, k)
    float v = src[(size_t)k * M + m];
    __nv_bfloat16 hi = __float2bfloat16(v);
    float lo = v - __bfloat162float(hi);
    wh[idx] = hi;
    wl[idx] = __float2bfloat16(lo);
}

// ---------------- activation pre-convert: fp32 -> bf16 hi/lo --------------
__device__ __forceinline__ void split4(float4 v, uint2& hv, uint2& lv)
{
    __nv_bfloat16 hx = __float2bfloat16(v.x);
    __nv_bfloat16 hy = __float2bfloat16(v.y);
    __nv_bfloat16 hz = __float2bfloat16(v.z);
    __nv_bfloat16 hw = __float2bfloat16(v.w);
    __nv_bfloat16 lx = __float2bfloat16(v.x - __bfloat162float(hx));
    __nv_bfloat16 ly = __float2bfloat16(v.y - __bfloat162float(hy));
    __nv_bfloat16 lz = __float2bfloat16(v.z - __bfloat162float(hz));
    __nv_bfloat16 lw = __float2bfloat16(v.w - __bfloat162float(hw));
    hv.x = ((uint32_t)__bfloat16_as_ushort(hy) << 16) | __bfloat16_as_ushort(hx);
    hv.y = ((uint32_t)__bfloat16_as_ushort(hw) << 16) | __bfloat16_as_ushort(hz);
    lv.x = ((uint32_t)__bfloat16_as_ushort(ly) << 16) | __bfloat16_as_ushort(lx);
    lv.y = ((uint32_t)__bfloat16_as_ushort(lw) << 16) | __bfloat16_as_ushort(lz);
}

__global__ void conv_x_kernel(const float* __restrict__ A,
                              __nv_bfloat16* __restrict__ oh, __nv_bfloat16* __restrict__ ol,
                              int total4)
{
    int i = blockIdx.x * blockDim.x + threadIdx.x;
    if (i >= total4) return;
    float4 v = *(const float4*)(A + (size_t)i * 4);
    uint2 hv, lv;
    split4(v, hv, lv);
    *(uint2*)(oh + (size_t)i * 4) = hv;
    *(uint2*)(ol + (size_t)i * 4) = lv;
}

// ---------------- generic WMMA bf16 hi/lo GEMM (KC=64 chunks) -------------
template <int K, bool BIAS>
__global__ void __launch_bounds__(256)
gemm_pre(const __nv_bfloat16* __restrict__ Ah, const __nv_bfloat16* __restrict__ Al,
         const __nv_bfloat16* __restrict__ Wth, const __nv_bfloat16* __restrict__ Wtl,
         const float* __restrict__ b1, const float* __restrict__ b2,
         float* __restrict__ C0,
         __nv_bfloat16* __restrict__ oh, __nv_bfloat16* __restrict__ ol,
         int n, int mout)
{
    constexpr int KC  = 64;
    constexpr int LDA = KC + 8;
    constexpr int NKC = K / KC;
    extern __shared__ __align__(16) char smem[];
    __nv_bfloat16* sAh = (__nv_bfloat16*)smem;
    __nv_bfloat16* sAl = sAh + 128 * LDA;
    __nv_bfloat16* sWh = sAl + 128 * LDA;
    __nv_bfloat16* sWl = sWh + 128 * LDA;

    const int tid = threadIdx.x;
    const int warp = tid >> 5;
    const int wr = warp >> 1;
    const int wc = warp & 1;
    const int rowBase = blockIdx.x * 128;
    const int colBase = blockIdx.y * 128;

    wmma::fragment<wmma::accumulator, 16, 16, 16, float> acc[2][4];
    #pragma unroll
    for (int i = 0; i < 2; i++)
        #pragma unroll
        for (int j = 0; j < 4; j++) wmma::fill_fragment(acc[i][j], 0.0f);

    for (int kc = 0; kc < NKC; kc++) {
        const int k0 = kc * KC;
        #pragma unroll
        for (int it = 0; it < 4; it++) {
            int idx = tid + it * 256;
            int r = idx >> 3, c8 = (idx & 7) * 8;
            int row = rowBase + r;
            uint4 hv = make_uint4(0u, 0u, 0u, 0u), lv = hv;
            if (row < n) {
                size_t g = (size_t)row * K + k0 + c8;
                hv = *(const uint4*)(Ah + g);
                lv = *(const uint4*)(Al + g);
            }
            *(uint4*)(sAh + r * LDA + c8) = hv;
            *(uint4*)(sAl + r * LDA + c8) = lv;
        }
        #pragma unroll
        for (int it = 0; it < 4; it++) {
            int idx = tid + it * 256;
            int r = idx >> 3, c8 = (idx & 7) * 8;
            size_t g = (size_t)(colBase + r) * K + k0 + c8;
            *(uint4*)(sWh + r * LDA + c8) = *(const uint4*)(Wth + g);
            *(uint4*)(sWl + r * LDA + c8) = *(const uint4*)(Wtl + g);
        }
        __syncthreads();

        #pragma unroll
        for (int ks = 0; ks < KC / 16; ks++) {
            wmma::fragment<wmma::matrix_a, 16, 16, 16, __nv_bfloat16, wmma::row_major> ah[2], al[2];
            wmma::fragment<wmma::matrix_b, 16, 16, 16, __nv_bfloat16, wmma::col_major> bh[4], bl[4];
            #pragma unroll
            for (int i = 0; i < 2; i++) {
                const __nv_bfloat16* p = sAh + (wr * 32 + i * 16) * LDA + ks * 16;
                wmma::load_matrix_sync(ah[i], p, LDA);
                wmma::load_matrix_sync(al[i], p + 128 * LDA, LDA);
            }
            #pragma unroll
            for (int j = 0; j < 4; j++) {
                const __nv_bfloat16* p = sWh + (wc * 64 + j * 16) * LDA + ks * 16;
                wmma::load_matrix_sync(bh[j], p, LDA);
                wmma::load_matrix_sync(bl[j], p + 128 * LDA, LDA);
            }
            #pragma unroll
            for (int i = 0; i < 2; i++)
                #pragma unroll
                for (int j = 0; j < 4; j++) {
                    wmma::mma_sync(acc[i][j], ah[i], bh[j], acc[i][j]);
                    wmma::mma_sync(acc[i][j], ah[i], bl[j], acc[i][j]);
                    wmma::mma_sync(acc[i][j], al[i], bh[j], acc[i][j]);
                }
        }
        __syncthreads();
    }

    float* sC = (float*)smem;                    // 128 x 132
    #pragma unroll
    for (int i = 0; i < 2; i++)
        #pragma unroll
        for (int j = 0; j < 4; j++)
            wmma::store_matrix_sync(sC + (wr * 32 + i * 16) * 132 + wc * 64 + j * 16,
                                    acc[i][j], 132, wmma::mem_row_major);
    __syncthreads();
    #pragma unroll
    for (int it = 0; it < 16; it++) {
        int idx = tid + it * 256;
        int r = idx >> 5, c4 = (idx & 31) * 4;
        int row = rowBase + r;
        if (row < n) {
            float4 v = *(float4*)(sC + r * 132 + c4);
            if (BIAS) {
                int col = colBase + c4;
                v.x += b1[col];     v.y += b1[col + 1];
                v.z += b1[col + 2]; v.w += b1[col + 3];
                if (b2) {
                    v.x += b2[col];     v.y += b2[col + 1];
                    v.z += b2[col + 2]; v.w += b2[col + 3];
                }
            }
            size_t g = (size_t)row * mout + colBase + c4;
            *(float4*)(C0 + g) = v;
            if (oh) {
                uint2 hv, lv;
                split4(v, hv, lv);
                *(uint2*)(oh + g) = hv;
                *(uint2*)(ol + g) = lv;
            }
        }
    }
}

// ---------------- fused QKV GEMM: A staged ONCE, W streamed per output ----
// K = 128. o=0 -> fp32 Q; o=1 (K), o=2 (V) -> packed fp16 KV.
__global__ void __launch_bounds__(256)
gemm_qkv(const __nv_bfloat16* __restrict__ Ah, const __nv_bfloat16* __restrict__ Al,
         const __nv_bfloat16* __restrict__ Wth, const __nv_bfloat16* __restrict__ Wtl,
         float* __restrict__ Qout, __half* __restrict__ kvout, int n)
{
    constexpr int K   = 128;
    constexpr int LDA = K + 8;          // 136
    extern __shared__ __align__(16) char smem[];
    __nv_bfloat16* sAh = (__nv_bfloat16*)smem;          // 128*136
    __nv_bfloat16* sAl = sAh + 128 * LDA;
    __nv_bfloat16* sWh = sAl + 128 * LDA;
    __nv_bfloat16* sWl = sWh + 128 * LDA;
    float*         sC  = (float*)sWh;                    // reuse W region (128x132 fp32)

    const int tid = threadIdx.x;
    const int warp = tid >> 5;
    const int wr = warp >> 1;
    const int wc = warp & 1;
    const int rowBase = blockIdx.x * 128;

    // stage full A (hi/lo) once
    #pragma unroll
    for (int it = 0; it < 8; it++) {
        int idx = tid + it * 256;               // 2048 uint4 per buffer
        int r = idx >> 4, c8 = (idx & 15) * 8;
        int row = rowBase + r;
        uint4 hv = make_uint4(0u, 0u, 0u, 0u), lv = hv;
        if (row < n) {
            size_t g = (size_t)row * K + c8;
            hv = *(const uint4*)(Ah + g);
            lv = *(const uint4*)(Al + g);
        }
        *(uint4*)(sAh + r * LDA + c8) = hv;
        *(uint4*)(sAl + r * LDA + c8) = lv;
    }

    for (int o = 0; o < 3; o++) {
        // stage W_o (full 128x128 hi/lo)
        const __nv_bfloat16* Wh_o = Wth + (size_t)o * (K * 128);
        const __nv_bfloat16* Wl_o = Wtl + (size_t)o * (K * 128);
        #pragma unroll
        for (int it = 0; it < 8; it++) {
            int idx = tid + it * 256;
            int r = idx >> 4, c8 = (idx & 15) * 8;
            size_t g = (size_t)r * K + c8;
            *(uint4*)(sWh + r * LDA + c8) = *(const uint4*)(Wh_o + g);
            *(uint4*)(sWl + r * LDA + c8) = *(const uint4*)(Wl_o + g);
        }
        __syncthreads();

        wmma::fragment<wmma::accumulator, 16, 16, 16, float> acc[2][4];
        #pragma unroll
        for (int i = 0; i < 2; i++)
            #pragma unroll
            for (int j = 0; j < 4; j++) wmma::fill_fragment(acc[i][j], 0.0f);

        #pragma unroll
        for (int ks = 0; ks < 8; ks++) {
            wmma::fragment<wmma::matrix_a, 16, 16, 16, __nv_bfloat16, wmma::row_major> ah[2], al[2];
            wmma::fragment<wmma::matrix_b, 16, 16, 16, __nv_bfloat16, wmma::col_major> bh[4], bl[4];
            #pragma unroll
            for (int i = 0; i < 2; i++) {
                const __nv_bfloat16* p = sAh + (wr * 32 + i * 16) * LDA + ks * 16;
                wmma::load_matrix_sync(ah[i], p, LDA);
                wmma::load_matrix_sync(al[i], p + 128 * LDA, LDA);
            }
            #pragma unroll
            for (int j = 0; j < 4; j++) {
                const __nv_bfloat16* p = sWh + (wc * 64 + j * 16) * LDA + ks * 16;
                wmma::load_matrix_sync(bh[j], p, LDA);
                wmma::load_matrix_sync(bl[j], p + 128 * LDA, LDA);
            }
            #pragma unroll
            for (int i = 0; i < 2; i++)
                #pragma unroll
                for (int j = 0; j < 4; j++) {
                    wmma::mma_sync(acc[i][j], ah[i], bh[j], acc[i][j]);
                    wmma::mma_sync(acc[i][j], ah[i], bl[j], acc[i][j]);
                    wmma::mma_sync(acc[i][j], al[i], bh[j], acc[i][j]);
                }
        }
        __syncthreads();   // all MMA reads of sW done before sC overwrite

        #pragma unroll
        for (int i = 0; i < 2; i++)
            #pragma unroll
            for (int j = 0; j < 4; j++)
                wmma::store_matrix_sync(sC + (wr * 32 + i * 16) * 132 + wc * 64 + j * 16,
                                        acc[i][j], 132, wmma::mem_row_major);
        __syncthreads();

        #pragma unroll
        for (int it = 0; it < 16; it++) {
            int idx = tid + it * 256;
            int r = idx >> 5, c4 = (idx & 31) * 4;
            int row = rowBase + r;
            if (row < n) {
                float4 v = *(float4*)(sC + r * 132 + c4);
                if (o == 0) {
                    *(float4*)(Qout + (size_t)row * 128 + c4) = v;
                } else {
                    __half2 h01 = __floats2half2_rn(v.x, v.y);
                    __half2 h23 = __floats2half2_rn(v.z, v.w);
                    uint2 st;
                    st.x = *(uint32_t*)&h01;
                    st.y = *(uint32_t*)&h23;
                    *(uint2*)(kvout + (size_t)row * 256 + (c4 >> 2) * 8 + ((o == 1) ? 0 : 4)) = st;
                }
            }
        }
        __syncthreads();   // epilogue reads of sC done before next W stage
    }
}

// ---------------- final GEMM: A staged once, 2 col-chunks of 128 ----------
__global__ void __launch_bounds__(256)
gemm_fin(const __nv_bfloat16* __restrict__ Ah, const __nv_bfloat16* __restrict__ Al,
         const __nv_bfloat16* __restrict__ Wth, const __nv_bfloat16* __restrict__ Wtl,
         const float* __restrict__ bias, float* __restrict__ C, int n)
{
    constexpr int K   = 128;
    constexpr int LDA = K + 8;          // 136
    extern __shared__ __align__(16) char smem[];
    __nv_bfloat16* sAh = (__nv_bfloat16*)smem;
    __nv_bfloat16* sAl = sAh + 128 * LDA;
    __nv_bfloat16* sWh = sAl + 128 * LDA;
    __nv_bfloat16* sWl = sWh + 128 * LDA;
    float*         sC  = (float*)sWh;

    const int tid = threadIdx.x;
    const int warp = tid >> 5;
    const int wr = warp >> 1;
    const int wc = warp & 1;
    const int rowBase = blockIdx.x * 128;

    #pragma unroll
    for (int it = 0; it < 8; it++) {
        int idx = tid + it * 256;
        int r = idx >> 4, c8 = (idx & 15) * 8;
        int row = rowBase + r;
        uint4 hv = make_uint4(0u, 0u, 0u, 0u), lv = hv;
        if (row < n) {
            size_t g = (size_t)row * K + c8;
            hv = *(const uint4*)(Ah + g);
            lv = *(const uint4*)(Al + g);
        }
        *(uint4*)(sAh + r * LDA + c8) = hv;
        *(uint4*)(sAl + r * LDA + c8) = lv;
    }

    for (int o = 0; o < 2; o++) {
        const __nv_bfloat16* Wh_o = Wth + (size_t)o * (K * 128);
        const __nv_bfloat16* Wl_o = Wtl + (size_t)o * (K * 128);
        #pragma unroll
        for (int it = 0; it < 8; it++) {
            int idx = tid + it * 256;
            int r = idx >> 4, c8 = (idx & 15) * 8;
            size_t g = (size_t)r * K + c8;
            *(uint4*)(sWh + r * LDA + c8) = *(const uint4*)(Wh_o + g);
            *(uint4*)(sWl + r * LDA + c8) = *(const uint4*)(Wl_o + g);
        }
        __syncthreads();

        wmma::fragment<wmma::accumulator, 16, 16, 16, float> acc[2][4];
        #pragma unroll
        for (int i = 0; i < 2; i++)
            #pragma unroll
            for (int j = 0; j < 4; j++) wmma::fill_fragment(acc[i][j], 0.0f);

        #pragma unroll
        for (int ks = 0; ks < 8; ks++) {
            wmma::fragment<wmma::matrix_a, 16, 16, 16, __nv_bfloat16, wmma::row_major> ah[2], al[2];
            wmma::fragment<wmma::matrix_b, 16, 16, 16, __nv_bfloat16, wmma::col_major> bh[4], bl[4];
            #pragma unroll
            for (int i = 0; i < 2; i++) {
                const __nv_bfloat16* p = sAh + (wr * 32 + i * 16) * LDA + ks * 16;
                wmma::load_matrix_sync(ah[i], p, LDA);
                wmma::load_matrix_sync(al[i], p + 128 * LDA, LDA);
            }
            #pragma unroll
            for (int j = 0; j < 4; j++) {
                const __nv_bfloat16* p = sWh + (wc * 64 + j * 16) * LDA + ks * 16;
                wmma::load_matrix_sync(bh[j], p, LDA);
                wmma::load_matrix_sync(bl[j], p + 128 * LDA, LDA);
            }
            #pragma unroll
            for (int i = 0; i < 2; i++)
                #pragma unroll
                for (int j = 0; j < 4; j++) {
                    wmma::mma_sync(acc[i][j], ah[i], bh[j], acc[i][j]);
                    wmma::mma_sync(acc[i][j], ah[i], bl[j], acc[i][j]);
                    wmma::mma_sync(acc[i][j], al[i], bh[j], acc[i][j]);
                }
        }
        __syncthreads();

        #pragma unroll
        for (int i = 0; i < 2; i++)
            #pragma unroll
            for (int j = 0; j < 4; j++)
                wmma::store_matrix_sync(sC + (wr * 32 + i * 16) * 132 + wc * 64 + j * 16,
                                        acc[i][j], 132, wmma::mem_row_major);
        __syncthreads();

        #pragma unroll
        for (int it = 0; it < 16; it++) {
            int idx = tid + it * 256;
            int r = idx >> 5, c4 = (idx & 31) * 4;
            int row = rowBase + r;
            if (row < n) {
                float4 v = *(float4*)(sC + r * 132 + c4);
                int col = o * 128 + c4;
                v.x += bias[col];     v.y += bias[col + 1];
                v.z += bias[col + 2]; v.w += bias[col + 3];
                *(float4*)(C + (size_t)row * 256 + col) = v;
            }
        }
        __syncthreads();
    }
}

// ---------------- warp-per-node agg + residual + LayerNorm (MLP=4) -------
__device__ __forceinline__ void agg_edge(uint4 kv, float4 q4, float4& acc, float& den)
{
    float2 kf0 = __half22float2(*(const __half2*)&kv.x);
    float2 kf1 = __half22float2(*(const __half2*)&kv.y);
    float2 vf0 = __half22float2(*(const __half2*)&kv.z);
    float2 vf1 = __half22float2(*(const __half2*)&kv.w);
    float d = q4.x * kf0.x;
    d = fmaf(q4.y, kf0.y, d);
    d = fmaf(q4.z, kf1.x, d);
    d = fmaf(q4.w, kf1.y, d);
    d += __shfl_xor_sync(0xffffffffu, d, 1);
    d += __shfl_xor_sync(0xffffffffu, d, 2);
    d = fminf(10.f, fmaxf(-10.f, d));
    float w = __expf(d);
    den += w;
    acc.x = fmaf(w, vf0.x, acc.x);
    acc.y = fmaf(w, vf0.y, acc.y);
    acc.z = fmaf(w, vf1.x, acc.z);
    acc.w = fmaf(w, vf1.y, acc.w);
}

__launch_bounds__(256)
__global__ void agg_ln_kernel(const float* __restrict__ Q, const __half* __restrict__ KV,
                              const float* __restrict__ emb,
                              const int* __restrict__ off, const int* __restrict__ colArr,
                              const float* __restrict__ lns, const float* __restrict__ lnb,
                              float* __restrict__ outp,
                              __nv_bfloat16* __restrict__ oh, __nv_bfloat16* __restrict__ ol,
                              int n)
{
    int gw = (blockIdx.x * blockDim.x + threadIdx.x) >> 5;   // local node id
    int lane = threadIdx.x & 31;
    if (gw >= n) return;
    const int base = gw * DDIM + lane * 4;
    const int koff = lane * 8;

    const float4 q4 = *(const float4*)(Q + base);
    float4 acc = make_float4(0.f, 0.f, 0.f, 0.f);
    float den = 0.f;

    int s = off[gw], e = off[gw + 1];
    int i = s;
    for (; i + 4 <= e; i += 4) {
        uint4 kv0 = *(const uint4*)(KV + (size_t)colArr[i]     * 256 + koff);
        uint4 kv1 = *(const uint4*)(KV + (size_t)colArr[i + 1] * 256 + koff);
        uint4 kv2 = *(const uint4*)(KV + (size_t)colArr[i + 2] * 256 + koff);
        uint4 kv3 = *(const uint4*)(KV + (size_t)colArr[i + 3] * 256 + koff);
        agg_edge(kv0, q4, acc, den);
        agg_edge(kv1, q4, acc, den);
        agg_edge(kv2, q4, acc, den);
        agg_edge(kv3, q4, acc, den);
    }
    for (; i < e; i++) {
        uint4 kv = *(const uint4*)(KV + (size_t)colArr[i] * 256 + koff);
        agg_edge(kv, q4, acc, den);
    }

    float inv = 1.f / (den + 1e-8f);
    float4 r = *(const float4*)(emb + base);
    r.x = fmaf(acc.x, inv, r.x);
    r.y = fmaf(acc.y, inv, r.y);
    r.z = fmaf(acc.z, inv, r.z);
    r.w = fmaf(acc.w, inv, r.w);

    float ss = r.x + r.y + r.z + r.w;
    #pragma unroll
    for (int o = 16; o; o >>= 1) ss += __shfl_xor_sync(0xffffffffu, ss, o);
    float mu = ss * (1.f / 128.f);

    float dx = r.x - mu, dy = r.y - mu, dz = r.z - mu, dw = r.w - mu;
    float vs = dx * dx + dy * dy + dz * dz + dw * dw;
    #pragma unroll
    for (int o = 16; o; o >>= 1) vs += __shfl_xor_sync(0xffffffffu, vs, o);
    float var = vs * (1.f / 128.f);
    float rstd = rsqrtf(var + 1e-6f);

    const float4 s4 = *(const float4*)(lns + lane * 4);
    const float4 b4 = *(const float4*)(lnb + lane * 4);
    float4 o4;
    o4.x = dx * rstd * s4.x + b4.x;
    o4.y = dy * rstd * s4.y + b4.y;
    o4.z = dz * rstd * s4.z + b4.z;
    o4.w = dw * rstd * s4.w + b4.w;
    if (outp) *(float4*)(outp + base) = o4;
    uint2 hv, lv;
    split4(o4, hv, lv);
    *(uint2*)(oh + base) = hv;
    *(uint2*)(ol + base) = lv;
}

// ---------------- launch ----------------
extern "C" void kernel_launch(void* const* d_in, const int* in_sizes, int n_in,
                              void* d_out, int out_size)
{
    const float* x    = (const float*)d_in[0];
    const void*  ei   = d_in[1];
    const float* Wp   = (const float*)d_in[2];
    const float* Wpb  = (const float*)d_in[3];
    const float* Wpos = (const float*)d_in[4];
    const float* q1   = (const float*)d_in[5];
    const float* k1   = (const float*)d_in[6];
    const float* v1   = (const float*)d_in[7];
    const float* l1s  = (const float*)d_in[8];
    const float* l1b  = (const float*)d_in[9];
    const float* q2   = (const float*)d_in[10];
    const float* k2   = (const float*)d_in[11];
    const float* v2   = (const float*)d_in[12];
    const float* l2s  = (const float*)d_in[13];
    const float* l2b  = (const float*)d_in[14];
    const float* invw = (const float*)d_in[15];
    const float* invb = (const float*)d_in[16];

    const int D   = in_sizes[3];            // 128
    const int GIN = in_sizes[2] / D;        // 256
    int n = in_sizes[0] / GIN;              // 50000
    int E = in_sizes[1] / 2;                // 800000
    if (n > NMAX) n = NMAX;
    if (E > EMAX) E = EMAX;
    (void)D; (void)n_in; (void)out_size;

    float *emb, *emb2, *Qb;
    __half *kv;
    int *degcur, *off, *col;
    __nv_bfloat16 *wh, *wl, *xh, *xl, *eh, *el;
    cudaGetSymbolAddress((void**)&emb,    g_emb);
    cudaGetSymbolAddress((void**)&emb2,   g_emb2);
    cudaGetSymbolAddress((void**)&Qb,     g_Q);
    cudaGetSymbolAddress((void**)&kv,     g_KV);
    cudaGetSymbolAddress((void**)&degcur, g_degcur);
    cudaGetSymbolAddress((void**)&off,    g_off);
    cudaGetSymbolAddress((void**)&col,    g_col);
    cudaGetSymbolAddress((void**)&wh,     g_wh);
    cudaGetSymbolAddress((void**)&wl,     g_wl);
    cudaGetSymbolAddress((void**)&xh,     g_xh);
    cudaGetSymbolAddress((void**)&xl,     g_xl);
    cudaGetSymbolAddress((void**)&eh,     g_eh);
    cudaGetSymbolAddress((void**)&el,     g_el);
    int* deg  = degcur;
    int* cur  = degcur + NMAX;
    int* hiOr = degcur + 2 * NMAX;

    const int SMEM_G = 4 * 128 * 72 * 2;    // 73728 (generic, KC=64)
    const int SMEM_Q = 4 * 128 * 136 * 2;   // 139264 (A + W fully staged)
    cudaFuncSetAttribute(gemm_pre<256, true>,
                         cudaFuncAttributeMaxDynamicSharedMemorySize, SMEM_G);
    cudaFuncSetAttribute(gemm_qkv,
                         cudaFuncAttributeMaxDynamicSharedMemorySize, SMEM_Q);
    cudaFuncSetAttribute(gemm_fin,
                         cudaFuncAttributeMaxDynamicSharedMemorySize, SMEM_Q);

    const int eb = (E + 255) / 256;
    const int gb = (n + 127) / 128;

    // node halves for agg<->gemm pipelining (h0 multiple of 128)
    const int h0 = ((n / 2 + 127) / 128) * 128;        // 25088
    const int h1 = n - h0;                             // 24912
    const int gb0 = h0 / 128, gb1 = (h1 + 127) / 128;
    const int ab0 = (h0 + 7) / 8, ab1 = (h1 + 7) / 8;

    // Streams/events: created ONCE on first call and reused (per-call creation
    // leaked driver pool memory and tripped the allocation guard).
    static cudaStream_t s2 = nullptr, s3 = nullptr;
    static cudaEvent_t evFork = nullptr, evJoin = nullptr, evConv = nullptr;
    static cudaEvent_t evQKV1 = nullptr, evA1 = nullptr, evB1 = nullptr;
    static cudaEvent_t evA2 = nullptr, evB2 = nullptr, evEnd = nullptr;
    if (s2 == nullptr) {
        cudaStreamCreateWithFlags(&s2, cudaStreamNonBlocking);
        cudaStreamCreateWithFlags(&s3, cudaStreamNonBlocking);
        cudaEventCreateWithFlags(&evFork, cudaEventDisableTiming);
        cudaEventCreateWithFlags(&evJoin, cudaEventDisableTiming);
        cudaEventCreateWithFlags(&evConv, cudaEventDisableTiming);
        cudaEventCreateWithFlags(&evQKV1, cudaEventDisableTiming);
        cudaEventCreateWithFlags(&evA1, cudaEventDisableTiming);
        cudaEventCreateWithFlags(&evB1, cudaEventDisableTiming);
        cudaEventCreateWithFlags(&evA2, cudaEventDisableTiming);
        cudaEventCreateWithFlags(&evB2, cudaEventDisableTiming);
        cudaEventCreateWithFlags(&evEnd, cudaEventDisableTiming);
    }

    cudaEventRecord(evFork, 0);
    cudaStreamWaitEvent(s2, evFork, 0);
    cudaStreamWaitEvent(s3, evFork, 0);

    // --- CSR branch (stream s2) ---
    cudaMemsetAsync(degcur, 0, (size_t)(2 * NMAX + 1) * sizeof(int), s2);
    detect_kernel<<<16, 256, 0, s2>>>((const unsigned int*)ei, E, hiOr);
    hist_kernel<<<eb, 256, 0, s2>>>(ei, E, n, deg, hiOr);
    scan_kernel<<<1, 1024, 0, s2>>>(deg, off, n);
    scatter_kernel<<<eb, 256, 0, s2>>>(ei, E, n, off, cur, col, hiOr);
    cudaEventRecord(evJoin, s2);

    // --- x conversion branch (stream s3, concurrent with prep_weights) ---
    const int xq = n * GIN / 4;
    conv_x_kernel<<<(xq + 255) / 256, 256, 0, s3>>>(x, xh, xl, xq);
    cudaEventRecord(evConv, s3);

    // --- main branch (default stream) ---
    prep_weights<<<640, 256>>>(Wp, q1, k1, v1, q2, k2, v2, invw, wh, wl);
    cudaStreamWaitEvent(0, evConv, 0);

    // input projection + bias + positional embedding (emits emb fp32 + hi/lo)
    gemm_pre<256, true><<<dim3(gb, 1), 256, SMEM_G>>>(
        xh, xl, wh, wl, Wpb, Wpos, emb, eh, el, n, 128);

    // layer 1 QKV (full, does not need CSR)
    gemm_qkv<<<gb, 256, SMEM_Q>>>(eh, el, wh + 32768, wl + 32768, Qb, kv, n);
    cudaEventRecord(evQKV1, 0);

    // ---- pipelined layer 1 agg -> layer 2 QKV (two node halves) ----
    // chain A on default stream (needs CSR); chain B on s2 (already after CSR,
    // needs QKV1).
    cudaStreamWaitEvent(0, evJoin, 0);
    cudaStreamWaitEvent(s2, evQKV1, 0);

    // chain A: half 0
    agg_ln_kernel<<<ab0, 256>>>(Qb, kv, emb, off, col, l1s, l1b,
                                emb2, eh, el, h0);
    gemm_qkv<<<gb0, 256, SMEM_Q>>>(eh, el, wh + 81920, wl + 81920, Qb, kv, h0);
    cudaEventRecord(evA1, 0);

    // chain B: half 1 (pointer offsets; off+h0 keeps global edge offsets)
    agg_ln_kernel<<<ab1, 256, 0, s2>>>(Qb + (size_t)h0 * 128, kv,
                                       emb + (size_t)h0 * 128, off + h0, col,
                                       l1s, l1b, emb2 + (size_t)h0 * 128,
                                       eh + (size_t)h0 * 128, el + (size_t)h0 * 128, h1);
    gemm_qkv<<<gb1, 256, SMEM_Q, s2>>>(eh + (size_t)h0 * 128, el + (size_t)h0 * 128,
                                       wh + 81920, wl + 81920,
                                       Qb + (size_t)h0 * 128, kv + (size_t)h0 * 256, h1);
    cudaEventRecord(evB1, s2);

    // join: layer-2 agg reads arbitrary neighbors' KV -> needs both halves
    cudaStreamWaitEvent(0, evB1, 0);
    cudaStreamWaitEvent(s2, evA1, 0);

    // ---- pipelined layer 2 agg -> final GEMM (two node halves) ----
    agg_ln_kernel<<<ab0, 256>>>(Qb, kv, emb2, off, col, l2s, l2b,
                                nullptr, eh, el, h0);
    gemm_fin<<<gb0, 256, SMEM_Q>>>(eh, el, wh + 131072, wl + 131072,
                                   invb, (float*)d_out, h0);

    agg_ln_kernel<<<ab1, 256, 0, s2>>>(Qb + (size_t)h0 * 128, kv,
                                       emb2 + (size_t)h0 * 128, off + h0, col,
                                       l2s, l2b, nullptr,
                                       eh + (size_t)h0 * 128, el + (size_t)h0 * 128, h1);
    gemm_fin<<<gb1, 256, SMEM_Q, s2>>>(eh + (size_t)h0 * 128, el + (size_t)h0 * 128,
                                       wh + 131072, wl + 131072,
                                       invb, (float*)d_out + (size_t)h0 * 256, h1);
    cudaEventRecord(evEnd, s2);
    cudaStreamWaitEvent(0, evEnd, 0);   // join all forked work back to capture stream
}